// round 10
// baseline (speedup 1.0000x reference)
#include <cuda_runtime.h>
#include <cuda_fp16.h>
#include <cstdint>

// Problem constants
#define BATCH 4
#define SEQ   2048
#define DMODEL 1024
#define NHEAD 16
#define HDIM  64
#define MROWS (BATCH * SEQ)          // 8192

// Scratch (device globals; allocation-free). All fp16.
__device__ __half g_qh[BATCH * NHEAD * SEQ * HDIM];     // [B,H,T,HD]
__device__ __half g_kh[BATCH * NHEAD * SEQ * HDIM];     // [B,H,T,HD]
__device__ __half g_vth[BATCH * NHEAD * HDIM * SEQ];    // [B,H,HD,T] (transposed)
__device__ __half g_attnh[MROWS * DMODEL];              // [B,T,D]
__device__ __half g_hidh[MROWS * DMODEL];               // fp16 hidden
__device__ __half g_wqkvt[3 * DMODEL * DMODEL];         // w_attn^T [3D][D]
__device__ __half g_wpt[DMODEL * DMODEL];               // w_proj^T [D][D]

// ---------------------------------------------------------------------------
// helpers
// ---------------------------------------------------------------------------
__device__ __forceinline__ unsigned smem_u32(const void* p) {
    return (unsigned)__cvta_generic_to_shared(p);
}
__device__ __forceinline__ void cp_async16(unsigned s, const void* g) {
    asm volatile("cp.async.cg.shared.global [%0], [%1], 16;\n" :: "r"(s), "l"(g));
}
#define CP_COMMIT() asm volatile("cp.async.commit_group;\n" ::: "memory")
#define CP_WAIT(n)  asm volatile("cp.async.wait_group %0;\n" :: "n"(n) : "memory")

__device__ __forceinline__ unsigned pack2h(float a, float b) {
    __half2 h = __floats2half2_rn(a, b);
    return *(unsigned*)&h;
}
__device__ __forceinline__ void mma_f16s(float* d, const unsigned* a, const unsigned* b) {
    asm volatile(
        "mma.sync.aligned.m16n8k16.row.col.f32.f16.f16.f32 "
        "{%0,%1,%2,%3},{%4,%5,%6,%7},{%8,%9},{%0,%1,%2,%3};\n"
        : "+f"(d[0]), "+f"(d[1]), "+f"(d[2]), "+f"(d[3])
        : "r"(a[0]), "r"(a[1]), "r"(a[2]), "r"(a[3]), "r"(b[0]), "r"(b[1]));
}
__device__ __forceinline__ void ldm_x4(unsigned* r, unsigned addr) {
    asm volatile(
        "ldmatrix.sync.aligned.m8n8.x4.shared.b16 {%0,%1,%2,%3}, [%4];"
        : "=r"(r[0]), "=r"(r[1]), "=r"(r[2]), "=r"(r[3]) : "r"(addr));
}

// ---------------------------------------------------------------------------
// Prepass 1: fp32 -> fp16 (vectorized)
// ---------------------------------------------------------------------------
__global__ __launch_bounds__(256) void f32_to_f16_kernel(
    const float* __restrict__ src, __half* __restrict__ dst, int n4)
{
    int i = blockIdx.x * blockDim.x + threadIdx.x;
    if (i < n4) {
        float4 v = ((const float4*)src)[i];
        __half2 h0 = __floats2half2_rn(v.x, v.y);
        __half2 h1 = __floats2half2_rn(v.z, v.w);
        ((uint2*)dst)[i] = make_uint2(*(unsigned*)&h0, *(unsigned*)&h1);
    }
}

// ---------------------------------------------------------------------------
// Prepass 2: transpose + convert: W [K][N] f32 -> Wt [N][K] f16
// ---------------------------------------------------------------------------
__global__ void transpose_to_f16_kernel(
    const float* __restrict__ src, __half* __restrict__ dst, int K, int N)
{
    __shared__ float t[32][33];
    int n = blockIdx.x * 32 + threadIdx.x;
    int k = blockIdx.y * 32 + threadIdx.y;
    t[threadIdx.y][threadIdx.x] = src[(size_t)k * N + n];
    __syncthreads();
    int no = blockIdx.x * 32 + threadIdx.y;
    int ko = blockIdx.y * 32 + threadIdx.x;
    dst[(size_t)no * K + ko] = __float2half_rn(t[threadIdx.x][threadIdx.y]);
}

// ---------------------------------------------------------------------------
// FP16 mma.sync GEMM (unchanged from R9): block 128x64, BK=64, 4 warps,
// 2-stage cp.async, 48KB static smem, 4 CTAs/SM, ldmatrix feeds.
// ---------------------------------------------------------------------------
template <int MODE>
__global__ __launch_bounds__(128, 4) void gemm_f16(
    const float* __restrict__ bias,
    float* __restrict__ C,
    int Kdim, int Ndim)
{
    __shared__ __align__(128) __half As[2][128 * 64];   // 2 x 16KB
    __shared__ __align__(128) __half Bs[2][64 * 64];    // 2 x 8KB

    const __half* A  = (MODE == 0) ? g_hidh  : g_attnh;
    const __half* Wt = (MODE == 0) ? g_wqkvt : g_wpt;

    const int m0 = blockIdx.y * 128;
    const int n0 = blockIdx.x * 64;
    const int tid  = threadIdx.x;
    const int lane = tid & 31;
    const int wid  = tid >> 5;
    const int wr = wid * 32;         // warp row offset (4 warps in M)
    const int g  = lane >> 2;
    const int t2 = (lane & 3) * 2;

    const int rA  = lane & 15;
    const int cA  = lane >> 4;
    const int selB = lane >> 3;
    const int rBo  = ((selB >> 1) << 3) + (lane & 7);
    const int cB   = selB & 1;

    const unsigned sA[2] = { smem_u32(As[0]), smem_u32(As[1]) };
    const unsigned sB[2] = { smem_u32(Bs[0]), smem_u32(Bs[1]) };

    float acc[2][8][4];
#pragma unroll
    for (int i = 0; i < 2; i++)
#pragma unroll
        for (int j = 0; j < 8; j++)
#pragma unroll
            for (int r = 0; r < 4; r++) acc[i][j][r] = 0.0f;

#define LOAD_TILE(KT_, ST_)                                                     \
    _Pragma("unroll")                                                           \
    for (int i_ = 0; i_ < 8; i_++) {                                            \
        const int c_ = tid + i_ * 128;                                          \
        const int row_ = c_ >> 3, ch_ = c_ & 7;                                 \
        const unsigned ph_ = row_ * 128 + (((ch_) ^ (row_ & 7)) << 4);          \
        cp_async16(sA[ST_] + ph_, &A[(size_t)(m0 + row_) * Kdim + (KT_) + ch_ * 8]); \
    }                                                                           \
    _Pragma("unroll")                                                           \
    for (int i_ = 0; i_ < 4; i_++) {                                            \
        const int c_ = tid + i_ * 128;                                          \
        const int row_ = c_ >> 3, ch_ = c_ & 7;                                 \
        const unsigned ph_ = row_ * 128 + (((ch_) ^ (row_ & 7)) << 4);          \
        cp_async16(sB[ST_] + ph_, &Wt[(size_t)(n0 + row_) * Kdim + (KT_) + ch_ * 8]); \
    }

    const int KT = Kdim >> 6;
    LOAD_TILE(0, 0);
    CP_COMMIT();

    for (int kt = 0; kt < KT; kt++) {
        const int st = kt & 1;
        CP_WAIT(0);
        __syncthreads();

        if (kt + 1 < KT) {
            LOAD_TILE((kt + 1) << 6, st ^ 1);
            CP_COMMIT();
        }

#pragma unroll
        for (int kc = 0; kc < 4; kc++) {
            unsigned af[2][4], bf[8][2];
#pragma unroll
            for (int i = 0; i < 2; i++) {
                const int row = wr + i * 16 + rA;
                const unsigned ph =
                    row * 128 + ((((kc << 1) | cA) ^ (row & 7)) << 4);
                ldm_x4(af[i], sA[st] + ph);
            }
#pragma unroll
            for (int jj = 0; jj < 4; jj++) {
                const int row = jj * 16 + rBo;
                const unsigned ph =
                    row * 128 + ((((kc << 1) | cB) ^ (row & 7)) << 4);
                unsigned q[4];
                ldm_x4(q, sB[st] + ph);
                bf[2 * jj][0]     = q[0];
                bf[2 * jj][1]     = q[1];
                bf[2 * jj + 1][0] = q[2];
                bf[2 * jj + 1][1] = q[3];
            }
#pragma unroll
            for (int i = 0; i < 2; i++)
#pragma unroll
                for (int j = 0; j < 8; j++) mma_f16s(acc[i][j], af[i], bf[j]);
        }
    }

#pragma unroll
    for (int i = 0; i < 2; i++) {
#pragma unroll
        for (int rr = 0; rr < 2; rr++) {
            const int row = m0 + wr + i * 16 + g + rr * 8;
#pragma unroll
            for (int j = 0; j < 8; j++) {
                const int col = n0 + j * 8 + t2;
                const float v0 = acc[i][j][rr * 2 + 0] + bias[col];
                const float v1 = acc[i][j][rr * 2 + 1] + bias[col + 1];
                if (MODE == 0) {
                    const int which = col >> 10;       // 0=q,1=k,2=v
                    const int d  = col & 1023;
                    const int h  = d >> 6;
                    const int hd = d & 63;
                    const int b  = row >> 11;
                    const int t  = row & 2047;
                    if (which < 2) {
                        __half* dst = (which == 0) ? g_qh : g_kh;
                        const size_t idx =
                            (((size_t)(b * NHEAD + h)) * SEQ + t) * HDIM + hd;
                        __half2 hv = __floats2half2_rn(v0, v1);
                        *(__half2*)&dst[idx] = hv;
                    } else {
                        const size_t idx =
                            (((size_t)(b * NHEAD + h)) * HDIM + hd) * SEQ + t;
                        g_vth[idx]       = __float2half_rn(v0);
                        g_vth[idx + SEQ] = __float2half_rn(v1);
                    }
                } else {
                    *(float2*)&C[(size_t)row * Ndim + col] = make_float2(v0, v1);
                }
            }
        }
    }
#undef LOAD_TILE
}

// ---------------------------------------------------------------------------
// Causal flash attention, FP16 mma.sync, ldmatrix feeds.
// Q tile 128, key tile 128, 8 warps (256 threads); per-warp 16 q-rows —
// identical per-warp stream to R9, but K/V loads + syncs amortized over 2x
// the queries and 16 warps/SM resident (2 CTAs x 8).
// smem: K[2] 2x16KB + V^T[2][2] 4x8KB = 64KB dynamic.
// ---------------------------------------------------------------------------
__global__ __launch_bounds__(256, 2) void flash_f16()
{
    extern __shared__ __align__(128) unsigned char fdsm_raw[];
    const unsigned base = (smem_u32(fdsm_raw) + 127u) & ~127u;
    const unsigned ksB[2] = { base, base + 16384 };
    const unsigned vtB[2][2] = {
        { base + 32768, base + 40960 },
        { base + 49152, base + 57344 }
    };

    const int qTile = blockIdx.x;        // 128-query tile
    const int bh    = blockIdx.y;

    const __half* Qh  = g_qh  + (size_t)bh * SEQ * HDIM;
    const __half* Kh  = g_kh  + (size_t)bh * SEQ * HDIM;
    const __half* Vth = g_vth + (size_t)bh * HDIM * SEQ;

    const int tid  = threadIdx.x;
    const int lane = tid & 31;
    const int wid  = tid >> 5;           // 0..7
    const int g    = lane >> 2;
    const int t2   = (lane & 3) * 2;
    const int q0   = qTile * 128;
    const int qr   = q0 + wid * 16 + g;

    const int selB = lane >> 3;
    const int rBo  = ((selB >> 1) << 3) + (lane & 7);
    const int cB   = selB & 1;

    // preload Q fragments (4 k16-chunks over HD=64)
    unsigned qf[4][4];
#pragma unroll
    for (int kc = 0; kc < 4; kc++) {
        const int ko = kc * 16 + t2;
        qf[kc][0] = *(const unsigned*)&Qh[(size_t)qr * HDIM + ko];
        qf[kc][1] = *(const unsigned*)&Qh[(size_t)(qr + 8) * HDIM + ko];
        qf[kc][2] = *(const unsigned*)&Qh[(size_t)qr * HDIM + ko + 8];
        qf[kc][3] = *(const unsigned*)&Qh[(size_t)(qr + 8) * HDIM + ko + 8];
    }

    float oacc[8][4];
#pragma unroll
    for (int j = 0; j < 8; j++)
#pragma unroll
        for (int r = 0; r < 4; r++) oacc[j][r] = 0.0f;
    float m0r = -1e30f, m1r = -1e30f, l0r = 0.0f, l1r = 0.0f;

    // loader (256 threads): K 128x8 chunks (4/thread); V halves 64x8 (2/thread)
#define LOAD_KV(K0_, ST_)                                                       \
    _Pragma("unroll")                                                           \
    for (int i_ = 0; i_ < 4; i_++) {                                            \
        const int c_ = tid + i_ * 256;                                          \
        const int r_ = c_ >> 3, ch_ = c_ & 7;                                   \
        const unsigned ph_ = r_ * 128 + (((ch_) ^ (r_ & 7)) << 4);              \
        cp_async16(ksB[ST_] + ph_, &Kh[(size_t)((K0_) + r_) * HDIM + ch_ * 8]); \
    }                                                                           \
    _Pragma("unroll")                                                           \
    for (int hf_ = 0; hf_ < 2; hf_++) {                                         \
        _Pragma("unroll")                                                       \
        for (int i_ = 0; i_ < 2; i_++) {                                        \
            const int c_ = tid + i_ * 256;                                      \
            const int r_ = c_ >> 3, ch_ = c_ & 7;                               \
            const unsigned ph_ = r_ * 128 + (((ch_) ^ (r_ & 7)) << 4);          \
            cp_async16(vtB[ST_][hf_] + ph_,                                     \
                       &Vth[(size_t)r_ * SEQ + (K0_) + hf_ * 64 + ch_ * 8]);    \
        }                                                                       \
    }

    const int ktN = qTile + 1;   // 128-key tiles 0..qTile
    LOAD_KV(0, 0);
    CP_COMMIT();

    for (int kt = 0; kt < ktN; kt++) {
        const int st = kt & 1;
        CP_WAIT(0);
        __syncthreads();   // tile kt resident & visible

        if (kt + 1 < ktN) {
            LOAD_KV((kt + 1) * 128, st ^ 1);
            CP_COMMIT();
        }

        // S = Q @ K^T  (16 n8 j-tiles = 128 keys)
        float sacc[16][4];
#pragma unroll
        for (int j = 0; j < 16; j++)
#pragma unroll
            for (int r = 0; r < 4; r++) sacc[j][r] = 0.0f;

#pragma unroll
        for (int kc = 0; kc < 4; kc++) {
            unsigned bf[16][2];
#pragma unroll
            for (int jj = 0; jj < 8; jj++) {
                const int row = jj * 16 + rBo;
                const unsigned ph =
                    row * 128 + ((((kc << 1) | cB) ^ (row & 7)) << 4);
                unsigned q[4];
                ldm_x4(q, ksB[st] + ph);
                bf[2 * jj][0]     = q[0];
                bf[2 * jj][1]     = q[1];
                bf[2 * jj + 1][0] = q[2];
                bf[2 * jj + 1][1] = q[3];
            }
#pragma unroll
            for (int j = 0; j < 16; j++) mma_f16s(sacc[j], qf[kc], bf[j]);
        }

        // scale + causal mask (diag tile only; global indices)
        const float scl = 0.125f;   // 1/sqrt(64)
        if (kt == ktN - 1) {
            const int r0 = q0 + wid * 16 + g;
            const int r1 = r0 + 8;
            const int kbase = kt * 128;
#pragma unroll
            for (int j = 0; j < 16; j++) {
                const int c = kbase + j * 8 + t2;
                sacc[j][0] = (c     > r0) ? -1e30f : sacc[j][0] * scl;
                sacc[j][1] = (c + 1 > r0) ? -1e30f : sacc[j][1] * scl;
                sacc[j][2] = (c     > r1) ? -1e30f : sacc[j][2] * scl;
                sacc[j][3] = (c + 1 > r1) ? -1e30f : sacc[j][3] * scl;
            }
        } else {
#pragma unroll
            for (int j = 0; j < 16; j++)
#pragma unroll
                for (int r = 0; r < 4; r++) sacc[j][r] *= scl;
        }

        // online softmax (rows owned by 4-lane groups; xor-reduce over 1,2)
        float rm0 = -1e30f, rm1 = -1e30f;
#pragma unroll
        for (int j = 0; j < 16; j++) {
            rm0 = fmaxf(rm0, fmaxf(sacc[j][0], sacc[j][1]));
            rm1 = fmaxf(rm1, fmaxf(sacc[j][2], sacc[j][3]));
        }
#pragma unroll
        for (int s = 1; s < 4; s <<= 1) {
            rm0 = fmaxf(rm0, __shfl_xor_sync(0xffffffffu, rm0, s));
            rm1 = fmaxf(rm1, __shfl_xor_sync(0xffffffffu, rm1, s));
        }
        const float mn0 = fmaxf(m0r, rm0);
        const float mn1 = fmaxf(m1r, rm1);
        const float al0 = __expf(m0r - mn0);
        const float al1 = __expf(m1r - mn1);
        float rs0 = 0.0f, rs1 = 0.0f;
#pragma unroll
        for (int j = 0; j < 16; j++) {
            sacc[j][0] = __expf(sacc[j][0] - mn0);
            sacc[j][1] = __expf(sacc[j][1] - mn0);
            sacc[j][2] = __expf(sacc[j][2] - mn1);
            sacc[j][3] = __expf(sacc[j][3] - mn1);
            rs0 += sacc[j][0] + sacc[j][1];
            rs1 += sacc[j][2] + sacc[j][3];
        }
#pragma unroll
        for (int s = 1; s < 4; s <<= 1) {
            rs0 += __shfl_xor_sync(0xffffffffu, rs0, s);
            rs1 += __shfl_xor_sync(0xffffffffu, rs1, s);
        }
        l0r = l0r * al0 + rs0;
        l1r = l1r * al1 + rs1;
        m0r = mn0;
        m1r = mn1;
#pragma unroll
        for (int j = 0; j < 8; j++) {
            oacc[j][0] *= al0;
            oacc[j][1] *= al0;
            oacc[j][2] *= al1;
            oacc[j][3] *= al1;
        }

        // O += P @ V : 8 k16-chunks over 128 keys; V half = kc>>2
#pragma unroll
        for (int kc = 0; kc < 8; kc++) {
            unsigned af[4];
            af[0] = pack2h(sacc[2 * kc][0],     sacc[2 * kc][1]);
            af[1] = pack2h(sacc[2 * kc][2],     sacc[2 * kc][3]);
            af[2] = pack2h(sacc[2 * kc + 1][0], sacc[2 * kc + 1][1]);
            af[3] = pack2h(sacc[2 * kc + 1][2], sacc[2 * kc + 1][3]);
            const unsigned vbase = vtB[st][kc >> 2];
            const int kci = kc & 3;
            unsigned bf[8][2];
#pragma unroll
            for (int jj = 0; jj < 4; jj++) {
                const int row = jj * 16 + rBo;
                const unsigned ph =
                    row * 128 + ((((kci << 1) | cB) ^ (row & 7)) << 4);
                unsigned q[4];
                ldm_x4(q, vbase + ph);
                bf[2 * jj][0]     = q[0];
                bf[2 * jj][1]     = q[1];
                bf[2 * jj + 1][0] = q[2];
                bf[2 * jj + 1][1] = q[3];
            }
#pragma unroll
            for (int j = 0; j < 8; j++) mma_f16s(oacc[j], af, bf[j]);
        }
        __syncthreads();   // all warps done with buffer st before refill
    }
#undef LOAD_KV

    // write merged-head output [B,T,D] as fp16 (proj consumes fp16)
    const int b = bh >> 4;
    const int h = bh & 15;
    const float il0 = 1.0f / l0r;
    const float il1 = 1.0f / l1r;
    const int t0 = q0 + wid * 16 + g;
    __half* base0 = g_attnh + ((size_t)(b * SEQ + t0)) * DMODEL + h * HDIM;
    __half* base1 = g_attnh + ((size_t)(b * SEQ + t0 + 8)) * DMODEL + h * HDIM;
#pragma unroll
    for (int j = 0; j < 8; j++) {
        const int c = j * 8 + t2;
        __half2 h0 = __floats2half2_rn(oacc[j][0] * il0, oacc[j][1] * il0);
        __half2 h1 = __floats2half2_rn(oacc[j][2] * il1, oacc[j][3] * il1);
        *(__half2*)&base0[c] = h0;
        *(__half2*)&base1[c] = h1;
    }
}

// ---------------------------------------------------------------------------
// kernel_launch
// inputs: 0 hidden_states [B,T,D] f32, 1 w_attn [D,3D], 2 b_attn [3D],
//         3 w_proj [D,D], 4 b_proj [D]; output [B,T,D] f32
// ---------------------------------------------------------------------------
extern "C" void kernel_launch(void* const* d_in, const int* in_sizes, int n_in,
                              void* d_out, int out_size)
{
    const float* hidden = (const float*)d_in[0];
    const float* w_attn = (const float*)d_in[1];
    const float* b_attn = (const float*)d_in[2];
    const float* w_proj = (const float*)d_in[3];
    const float* b_proj = (const float*)d_in[4];
    float* out = (float*)d_out;

    const int FDSM = 65536 + 128;   // flash: 64KB payload + align slack
    cudaFuncSetAttribute(flash_f16, cudaFuncAttributeMaxDynamicSharedMemorySize, FDSM);

    // 0) prepass: fp16 convert + weight transpose
    {
        __half* d_hid; cudaGetSymbolAddress((void**)&d_hid, g_hidh);
        __half* d_wq;  cudaGetSymbolAddress((void**)&d_wq,  g_wqkvt);
        __half* d_wp;  cudaGetSymbolAddress((void**)&d_wp,  g_wpt);
        f32_to_f16_kernel<<<(MROWS * DMODEL / 4 + 255) / 256, 256>>>(
            hidden, d_hid, MROWS * DMODEL / 4);
        transpose_to_f16_kernel<<<dim3(3 * DMODEL / 32, DMODEL / 32), dim3(32, 32)>>>(
            w_attn, d_wq, DMODEL, 3 * DMODEL);
        transpose_to_f16_kernel<<<dim3(DMODEL / 32, DMODEL / 32), dim3(32, 32)>>>(
            w_proj, d_wp, DMODEL, DMODEL);
    }

    // 1) QKV GEMM + bias + head split
    gemm_f16<0><<<dim3(3 * DMODEL / 64, MROWS / 128), 128>>>(
        b_attn, nullptr, DMODEL, 3 * DMODEL);

    // 2) causal flash attention (q-tile 128, key-tile 128, 8 warps)
    flash_f16<<<dim3(SEQ / 128, BATCH * NHEAD), 256, FDSM>>>();

    // 3) output projection + bias (fp32 out)
    gemm_f16<1><<<dim3(DMODEL / 64, MROWS / 128), 128>>>(
        b_proj, out, DMODEL, DMODEL);
}

// round 13
// speedup vs baseline: 1.0692x; 1.0692x over previous
#include <cuda_runtime.h>
#include <cuda_fp16.h>
#include <cstdint>

// Problem constants
#define BATCH 4
#define SEQ   2048
#define DMODEL 1024
#define NHEAD 16
#define HDIM  64
#define MROWS (BATCH * SEQ)          // 8192

// Scratch (device globals; allocation-free). All fp16.
__device__ __half g_qh[BATCH * NHEAD * SEQ * HDIM];     // [B,H,T,HD]
__device__ __half g_kh[BATCH * NHEAD * SEQ * HDIM];     // [B,H,T,HD]
__device__ __half g_vth[BATCH * NHEAD * HDIM * SEQ];    // [B,H,HD,T] (transposed)
__device__ __half g_attnh[MROWS * DMODEL];              // [B,T,D]
__device__ __half g_hidh[MROWS * DMODEL];               // fp16 hidden
__device__ __half g_wqkvt[3 * DMODEL * DMODEL];         // w_attn^T [3D][D]
__device__ __half g_wpt[DMODEL * DMODEL];               // w_proj^T [D][D]

// ---------------------------------------------------------------------------
// helpers
// ---------------------------------------------------------------------------
__device__ __forceinline__ unsigned smem_u32(const void* p) {
    return (unsigned)__cvta_generic_to_shared(p);
}
__device__ __forceinline__ void cp_async16(unsigned s, const void* g) {
    asm volatile("cp.async.cg.shared.global [%0], [%1], 16;\n" :: "r"(s), "l"(g));
}
#define CP_COMMIT() asm volatile("cp.async.commit_group;\n" ::: "memory")
#define CP_WAIT(n)  asm volatile("cp.async.wait_group %0;\n" :: "n"(n) : "memory")

__device__ __forceinline__ unsigned pack2h(float a, float b) {
    __half2 h = __floats2half2_rn(a, b);
    return *(unsigned*)&h;
}
__device__ __forceinline__ void mma_f16s(float* d, const unsigned* a, const unsigned* b) {
    asm volatile(
        "mma.sync.aligned.m16n8k16.row.col.f32.f16.f16.f32 "
        "{%0,%1,%2,%3},{%4,%5,%6,%7},{%8,%9},{%0,%1,%2,%3};\n"
        : "+f"(d[0]), "+f"(d[1]), "+f"(d[2]), "+f"(d[3])
        : "r"(a[0]), "r"(a[1]), "r"(a[2]), "r"(a[3]), "r"(b[0]), "r"(b[1]));
}
__device__ __forceinline__ void ldm_x4(unsigned* r, unsigned addr) {
    asm volatile(
        "ldmatrix.sync.aligned.m8n8.x4.shared.b16 {%0,%1,%2,%3}, [%4];"
        : "=r"(r[0]), "=r"(r[1]), "=r"(r[2]), "=r"(r[3]) : "r"(addr));
}

// ---------------------------------------------------------------------------
// Prepass 1: fp32 -> fp16 (vectorized)
// ---------------------------------------------------------------------------
__global__ __launch_bounds__(256) void f32_to_f16_kernel(
    const float* __restrict__ src, __half* __restrict__ dst, int n4)
{
    int i = blockIdx.x * blockDim.x + threadIdx.x;
    if (i < n4) {
        float4 v = ((const float4*)src)[i];
        __half2 h0 = __floats2half2_rn(v.x, v.y);
        __half2 h1 = __floats2half2_rn(v.z, v.w);
        ((uint2*)dst)[i] = make_uint2(*(unsigned*)&h0, *(unsigned*)&h1);
    }
}

// ---------------------------------------------------------------------------
// Prepass 2 (merged): transpose+convert both weights in one launch.
// z=0: w_attn [D][3D] -> g_wqkvt [3D][D]   (grid.x uses all 96 tiles)
// z=1: w_proj [D][D]  -> g_wpt  [D][D]     (grid.x tiles >=32 idle)
// ---------------------------------------------------------------------------
__global__ void transpose_both_kernel(
    const float* __restrict__ w_attn, const float* __restrict__ w_proj)
{
    __shared__ float t[32][33];
    const int z = blockIdx.z;
    const int N = z ? DMODEL : 3 * DMODEL;
    if (z && blockIdx.x >= DMODEL / 32) return;
    const float* src = z ? w_proj : w_attn;
    __half* dst = z ? g_wpt : g_wqkvt;

    int n = blockIdx.x * 32 + threadIdx.x;
    int k = blockIdx.y * 32 + threadIdx.y;
    t[threadIdx.y][threadIdx.x] = src[(size_t)k * N + n];
    __syncthreads();
    int no = blockIdx.x * 32 + threadIdx.y;
    int ko = blockIdx.y * 32 + threadIdx.x;
    dst[(size_t)no * DMODEL + ko] = __float2half_rn(t[threadIdx.x][threadIdx.y]);
}

// ---------------------------------------------------------------------------
// FP16 mma.sync GEMM: block 128x64, BK=64, 4 warps (warp tile 32x64),
// 2-stage cp.async, 48KB static smem, 4 CTAs/SM, ldmatrix feeds.
// ldmatrix addresses hoisted: addr(kc) = base ^ (kc<<5).
// ---------------------------------------------------------------------------
template <int MODE>
__global__ __launch_bounds__(128, 4) void gemm_f16(
    const float* __restrict__ bias,
    float* __restrict__ C,
    int Kdim, int Ndim)
{
    __shared__ __align__(128) __half As[2][128 * 64];   // 2 x 16KB
    __shared__ __align__(128) __half Bs[2][64 * 64];    // 2 x 8KB

    const __half* A  = (MODE == 0) ? g_hidh  : g_attnh;
    const __half* Wt = (MODE == 0) ? g_wqkvt : g_wpt;

    const int m0 = blockIdx.y * 128;
    const int n0 = blockIdx.x * 64;
    const int tid  = threadIdx.x;
    const int lane = tid & 31;
    const int wid  = tid >> 5;
    const int wr = wid * 32;         // warp row offset (4 warps in M)
    const int g  = lane >> 2;
    const int t2 = (lane & 3) * 2;

    const int rA  = lane & 15;
    const int cA  = lane >> 4;
    const int selB = lane >> 3;
    const int rBo  = ((selB >> 1) << 3) + (lane & 7);
    const int cB   = selB & 1;

    const unsigned sA[2] = { smem_u32(As[0]), smem_u32(As[1]) };
    const unsigned sB[2] = { smem_u32(Bs[0]), smem_u32(Bs[1]) };

    // kc-invariant ldmatrix base offsets (XOR with kc<<5 per chunk)
    unsigned pA[2], pB[4];
#pragma unroll
    for (int i = 0; i < 2; i++) {
        const int row = wr + i * 16 + rA;
        pA[i] = row * 128 + ((cA ^ (row & 7)) << 4);
    }
#pragma unroll
    for (int jj = 0; jj < 4; jj++) {
        const int row = jj * 16 + rBo;
        pB[jj] = row * 128 + ((cB ^ (row & 7)) << 4);
    }

    float acc[2][8][4];
#pragma unroll
    for (int i = 0; i < 2; i++)
#pragma unroll
        for (int j = 0; j < 8; j++)
#pragma unroll
            for (int r = 0; r < 4; r++) acc[i][j][r] = 0.0f;

#define LOAD_TILE(KT_, ST_)                                                     \
    _Pragma("unroll")                                                           \
    for (int i_ = 0; i_ < 8; i_++) {                                            \
        const int c_ = tid + i_ * 128;                                          \
        const int row_ = c_ >> 3, ch_ = c_ & 7;                                 \
        const unsigned ph_ = row_ * 128 + (((ch_) ^ (row_ & 7)) << 4);          \
        cp_async16(sA[ST_] + ph_, &A[(size_t)(m0 + row_) * Kdim + (KT_) + ch_ * 8]); \
    }                                                                           \
    _Pragma("unroll")                                                           \
    for (int i_ = 0; i_ < 4; i_++) {                                            \
        const int c_ = tid + i_ * 128;                                          \
        const int row_ = c_ >> 3, ch_ = c_ & 7;                                 \
        const unsigned ph_ = row_ * 128 + (((ch_) ^ (row_ & 7)) << 4);          \
        cp_async16(sB[ST_] + ph_, &Wt[(size_t)(n0 + row_) * Kdim + (KT_) + ch_ * 8]); \
    }

    const int KT = Kdim >> 6;
    LOAD_TILE(0, 0);
    CP_COMMIT();

    for (int kt = 0; kt < KT; kt++) {
        const int st = kt & 1;
        CP_WAIT(0);
        __syncthreads();

        if (kt + 1 < KT) {
            LOAD_TILE((kt + 1) << 6, st ^ 1);
            CP_COMMIT();
        }

        const unsigned aAdr0 = sA[st] + pA[0];
        const unsigned aAdr1 = sA[st] + pA[1];
        const unsigned bAdr0 = sB[st] + pB[0];
        const unsigned bAdr1 = sB[st] + pB[1];
        const unsigned bAdr2 = sB[st] + pB[2];
        const unsigned bAdr3 = sB[st] + pB[3];

#pragma unroll
        for (int kc = 0; kc < 4; kc++) {
            const unsigned kx = kc << 5;
            unsigned af[2][4], bf[8][2];
            ldm_x4(af[0], aAdr0 ^ kx);
            ldm_x4(af[1], aAdr1 ^ kx);
            {
                unsigned q[4];
                ldm_x4(q, bAdr0 ^ kx);
                bf[0][0] = q[0]; bf[0][1] = q[1]; bf[1][0] = q[2]; bf[1][1] = q[3];
                ldm_x4(q, bAdr1 ^ kx);
                bf[2][0] = q[0]; bf[2][1] = q[1]; bf[3][0] = q[2]; bf[3][1] = q[3];
                ldm_x4(q, bAdr2 ^ kx);
                bf[4][0] = q[0]; bf[4][1] = q[1]; bf[5][0] = q[2]; bf[5][1] = q[3];
                ldm_x4(q, bAdr3 ^ kx);
                bf[6][0] = q[0]; bf[6][1] = q[1]; bf[7][0] = q[2]; bf[7][1] = q[3];
            }
#pragma unroll
            for (int i = 0; i < 2; i++)
#pragma unroll
                for (int j = 0; j < 8; j++) mma_f16s(acc[i][j], af[i], bf[j]);
        }
    }

#pragma unroll
    for (int i = 0; i < 2; i++) {
#pragma unroll
        for (int rr = 0; rr < 2; rr++) {
            const int row = m0 + wr + i * 16 + g + rr * 8;
#pragma unroll
            for (int j = 0; j < 8; j++) {
                const int col = n0 + j * 8 + t2;
                const float v0 = acc[i][j][rr * 2 + 0] + bias[col];
                const float v1 = acc[i][j][rr * 2 + 1] + bias[col + 1];
                if (MODE == 0) {
                    const int which = col >> 10;       // 0=q,1=k,2=v
                    const int d  = col & 1023;
                    const int h  = d >> 6;
                    const int hd = d & 63;
                    const int b  = row >> 11;
                    const int t  = row & 2047;
                    if (which < 2) {
                        __half* dst = (which == 0) ? g_qh : g_kh;
                        const size_t idx =
                            (((size_t)(b * NHEAD + h)) * SEQ + t) * HDIM + hd;
                        __half2 hv = __floats2half2_rn(v0, v1);
                        *(__half2*)&dst[idx] = hv;
                    } else {
                        const size_t idx =
                            (((size_t)(b * NHEAD + h)) * HDIM + hd) * SEQ + t;
                        g_vth[idx]       = __float2half_rn(v0);
                        g_vth[idx + SEQ] = __float2half_rn(v1);
                    }
                } else {
                    *(float2*)&C[(size_t)row * Ndim + col] = make_float2(v0, v1);
                }
            }
        }
    }
#undef LOAD_TILE
}

// ---------------------------------------------------------------------------
// Causal flash attention (R9 config): Q tile 64, key tile 128, 128 threads
// (4 warps), double-buffered cp.async, 64KB dynamic smem, 3 CTAs/SM.
// ldmatrix addresses hoisted per tile: addr(kc) = base ^ (kc<<5).
// ---------------------------------------------------------------------------
__global__ __launch_bounds__(128, 3) void flash_f16()
{
    extern __shared__ __align__(128) unsigned char fdsm_raw[];
    const unsigned base = (smem_u32(fdsm_raw) + 127u) & ~127u;
    const unsigned ksB[2] = { base, base + 16384 };
    const unsigned vtB[2][2] = {
        { base + 32768, base + 40960 },
        { base + 49152, base + 57344 }
    };

    const int qTile = blockIdx.x;
    const int bh    = blockIdx.y;

    const __half* Qh  = g_qh  + (size_t)bh * SEQ * HDIM;
    const __half* Kh  = g_kh  + (size_t)bh * SEQ * HDIM;
    const __half* Vth = g_vth + (size_t)bh * HDIM * SEQ;

    const int tid  = threadIdx.x;
    const int lane = tid & 31;
    const int wid  = tid >> 5;
    const int g    = lane >> 2;
    const int t2   = (lane & 3) * 2;
    const int q0   = qTile * 64;
    const int qr   = q0 + wid * 16 + g;

    const int selB = lane >> 3;
    const int rBo  = ((selB >> 1) << 3) + (lane & 7);
    const int cB   = selB & 1;

    // kc-invariant ldmatrix base offsets (8 K-row groups; first 4 reused for V)
    unsigned pK[8];
#pragma unroll
    for (int jj = 0; jj < 8; jj++) {
        const int row = jj * 16 + rBo;
        pK[jj] = row * 128 + ((cB ^ (row & 7)) << 4);
    }

    // preload Q fragments (4 k16-chunks over HD=64)
    unsigned qf[4][4];
#pragma unroll
    for (int kc = 0; kc < 4; kc++) {
        const int ko = kc * 16 + t2;
        qf[kc][0] = *(const unsigned*)&Qh[(size_t)qr * HDIM + ko];
        qf[kc][1] = *(const unsigned*)&Qh[(size_t)(qr + 8) * HDIM + ko];
        qf[kc][2] = *(const unsigned*)&Qh[(size_t)qr * HDIM + ko + 8];
        qf[kc][3] = *(const unsigned*)&Qh[(size_t)(qr + 8) * HDIM + ko + 8];
    }

    float oacc[8][4];
#pragma unroll
    for (int j = 0; j < 8; j++)
#pragma unroll
        for (int r = 0; r < 4; r++) oacc[j][r] = 0.0f;
    float m0r = -1e30f, m1r = -1e30f, l0r = 0.0f, l1r = 0.0f;

#define LOAD_KV(K0_, ST_)                                                       \
    _Pragma("unroll")                                                           \
    for (int i_ = 0; i_ < 8; i_++) {                                            \
        const int c_ = tid + i_ * 128;                                          \
        const int r_ = c_ >> 3, ch_ = c_ & 7;                                   \
        const unsigned ph_ = r_ * 128 + (((ch_) ^ (r_ & 7)) << 4);              \
        cp_async16(ksB[ST_] + ph_, &Kh[(size_t)((K0_) + r_) * HDIM + ch_ * 8]); \
    }                                                                           \
    _Pragma("unroll")                                                           \
    for (int hf_ = 0; hf_ < 2; hf_++) {                                         \
        _Pragma("unroll")                                                       \
        for (int i_ = 0; i_ < 4; i_++) {                                        \
            const int c_ = tid + i_ * 128;                                      \
            const int r_ = c_ >> 3, ch_ = c_ & 7;                               \
            const unsigned ph_ = r_ * 128 + (((ch_) ^ (r_ & 7)) << 4);          \
            cp_async16(vtB[ST_][hf_] + ph_,                                     \
                       &Vth[(size_t)r_ * SEQ + (K0_) + hf_ * 64 + ch_ * 8]);    \
        }                                                                       \
    }

    const int ktN = (qTile >> 1) + 1;   // 128-key tiles
    LOAD_KV(0, 0);
    CP_COMMIT();

    for (int kt = 0; kt < ktN; kt++) {
        const int st = kt & 1;
        CP_WAIT(0);
        __syncthreads();   // tile kt resident & visible

        if (kt + 1 < ktN) {
            LOAD_KV((kt + 1) * 128, st ^ 1);
            CP_COMMIT();
        }

        // S = Q @ K^T  (16 n8 j-tiles = 128 keys)
        float sacc[16][4];
#pragma unroll
        for (int j = 0; j < 16; j++)
#pragma unroll
            for (int r = 0; r < 4; r++) sacc[j][r] = 0.0f;

#pragma unroll
        for (int kc = 0; kc < 4; kc++) {
            const unsigned kx = kc << 5;
            unsigned bf[16][2];
#pragma unroll
            for (int jj = 0; jj < 8; jj++) {
                unsigned q[4];
                ldm_x4(q, (ksB[st] + pK[jj]) ^ kx);
                bf[2 * jj][0]     = q[0];
                bf[2 * jj][1]     = q[1];
                bf[2 * jj + 1][0] = q[2];
                bf[2 * jj + 1][1] = q[3];
            }
#pragma unroll
            for (int j = 0; j < 16; j++) mma_f16s(sacc[j], qf[kc], bf[j]);
        }

        // scale + causal mask (last tile only; global indices)
        const float scl = 0.125f;   // 1/sqrt(64)
        if (kt == ktN - 1) {
            const int r0 = q0 + wid * 16 + g;
            const int r1 = r0 + 8;
            const int kbase = kt * 128;
#pragma unroll
            for (int j = 0; j < 16; j++) {
                const int c = kbase + j * 8 + t2;
                sacc[j][0] = (c     > r0) ? -1e30f : sacc[j][0] * scl;
                sacc[j][1] = (c + 1 > r0) ? -1e30f : sacc[j][1] * scl;
                sacc[j][2] = (c     > r1) ? -1e30f : sacc[j][2] * scl;
                sacc[j][3] = (c + 1 > r1) ? -1e30f : sacc[j][3] * scl;
            }
        } else {
#pragma unroll
            for (int j = 0; j < 16; j++)
#pragma unroll
                for (int r = 0; r < 4; r++) sacc[j][r] *= scl;
        }

        // online softmax (rows owned by 4-lane groups; xor-reduce over 1,2)
        float rm0 = -1e30f, rm1 = -1e30f;
#pragma unroll
        for (int j = 0; j < 16; j++) {
            rm0 = fmaxf(rm0, fmaxf(sacc[j][0], sacc[j][1]));
            rm1 = fmaxf(rm1, fmaxf(sacc[j][2], sacc[j][3]));
        }
#pragma unroll
        for (int s = 1; s < 4; s <<= 1) {
            rm0 = fmaxf(rm0, __shfl_xor_sync(0xffffffffu, rm0, s));
            rm1 = fmaxf(rm1, __shfl_xor_sync(0xffffffffu, rm1, s));
        }
        const float mn0 = fmaxf(m0r, rm0);
        const float mn1 = fmaxf(m1r, rm1);
        const float al0 = __expf(m0r - mn0);
        const float al1 = __expf(m1r - mn1);
        float rs0 = 0.0f, rs1 = 0.0f;
#pragma unroll
        for (int j = 0; j < 16; j++) {
            sacc[j][0] = __expf(sacc[j][0] - mn0);
            sacc[j][1] = __expf(sacc[j][1] - mn0);
            sacc[j][2] = __expf(sacc[j][2] - mn1);
            sacc[j][3] = __expf(sacc[j][3] - mn1);
            rs0 += sacc[j][0] + sacc[j][1];
            rs1 += sacc[j][2] + sacc[j][3];
        }
#pragma unroll
        for (int s = 1; s < 4; s <<= 1) {
            rs0 += __shfl_xor_sync(0xffffffffu, rs0, s);
            rs1 += __shfl_xor_sync(0xffffffffu, rs1, s);
        }
        l0r = l0r * al0 + rs0;
        l1r = l1r * al1 + rs1;
        m0r = mn0;
        m1r = mn1;
#pragma unroll
        for (int j = 0; j < 8; j++) {
            oacc[j][0] *= al0;
            oacc[j][1] *= al0;
            oacc[j][2] *= al1;
            oacc[j][3] *= al1;
        }

        // O += P @ V : 8 k16-chunks over 128 keys; V half = kc>>2
        const unsigned v0Adr = vtB[st][0];
        const unsigned v1Adr = vtB[st][1];
#pragma unroll
        for (int kc = 0; kc < 8; kc++) {
            unsigned af[4];
            af[0] = pack2h(sacc[2 * kc][0],     sacc[2 * kc][1]);
            af[1] = pack2h(sacc[2 * kc][2],     sacc[2 * kc][3]);
            af[2] = pack2h(sacc[2 * kc + 1][0], sacc[2 * kc + 1][1]);
            af[3] = pack2h(sacc[2 * kc + 1][2], sacc[2 * kc + 1][3]);
            const unsigned vbase = (kc < 4) ? v0Adr : v1Adr;
            const unsigned kx = (kc & 3) << 5;
            unsigned bf[8][2];
#pragma unroll
            for (int jj = 0; jj < 4; jj++) {
                unsigned q[4];
                ldm_x4(q, (vbase + pK[jj]) ^ kx);
                bf[2 * jj][0]     = q[0];
                bf[2 * jj][1]     = q[1];
                bf[2 * jj + 1][0] = q[2];
                bf[2 * jj + 1][1] = q[3];
            }
#pragma unroll
            for (int j = 0; j < 8; j++) mma_f16s(oacc[j], af, bf[j]);
        }
        __syncthreads();   // all warps done with buffer st before refill
    }
#undef LOAD_KV

    // write merged-head output [B,T,D] as fp16 (proj consumes fp16)
    const int b = bh >> 4;
    const int h = bh & 15;
    const float il0 = 1.0f / l0r;
    const float il1 = 1.0f / l1r;
    const int t0 = q0 + wid * 16 + g;
    __half* base0 = g_attnh + ((size_t)(b * SEQ + t0)) * DMODEL + h * HDIM;
    __half* base1 = g_attnh + ((size_t)(b * SEQ + t0 + 8)) * DMODEL + h * HDIM;
#pragma unroll
    for (int j = 0; j < 8; j++) {
        const int c = j * 8 + t2;
        __half2 h0 = __floats2half2_rn(oacc[j][0] * il0, oacc[j][1] * il0);
        __half2 h1 = __floats2half2_rn(oacc[j][2] * il1, oacc[j][3] * il1);
        *(__half2*)&base0[c] = h0;
        *(__half2*)&base1[c] = h1;
    }
}

// ---------------------------------------------------------------------------
// kernel_launch
// inputs: 0 hidden_states [B,T,D] f32, 1 w_attn [D,3D], 2 b_attn [3D],
//         3 w_proj [D,D], 4 b_proj [D]; output [B,T,D] f32
// ---------------------------------------------------------------------------
extern "C" void kernel_launch(void* const* d_in, const int* in_sizes, int n_in,
                              void* d_out, int out_size)
{
    const float* hidden = (const float*)d_in[0];
    const float* w_attn = (const float*)d_in[1];
    const float* b_attn = (const float*)d_in[2];
    const float* w_proj = (const float*)d_in[3];
    const float* b_proj = (const float*)d_in[4];
    float* out = (float*)d_out;

    const int FDSM = 65536 + 128;   // flash: 64KB payload + align slack
    cudaFuncSetAttribute(flash_f16, cudaFuncAttributeMaxDynamicSharedMemorySize, FDSM);

    // 0) prepass: fp16 convert + merged weight transposes
    {
        __half* d_hid; cudaGetSymbolAddress((void**)&d_hid, g_hidh);
        f32_to_f16_kernel<<<(MROWS * DMODEL / 4 + 255) / 256, 256>>>(
            hidden, d_hid, MROWS * DMODEL / 4);
        transpose_both_kernel<<<dim3(3 * DMODEL / 32, DMODEL / 32, 2), dim3(32, 32)>>>(
            w_attn, w_proj);
    }

    // 1) QKV GEMM + bias + head split (128x64 blocks, 4 CTAs/SM)
    gemm_f16<0><<<dim3(3 * DMODEL / 64, MROWS / 128), 128>>>(
        b_attn, nullptr, DMODEL, 3 * DMODEL);

    // 2) causal flash attention (q-tile 64, key-tile 128)
    flash_f16<<<dim3(SEQ / 64, BATCH * NHEAD), 128, FDSM>>>();

    // 3) output projection + bias (fp32 out)
    gemm_f16<1><<<dim3(DMODEL / 64, MROWS / 128), 128>>>(
        b_proj, out, DMODEL, DMODEL);
}

// round 14
// speedup vs baseline: 1.1202x; 1.0477x over previous
#include <cuda_runtime.h>
#include <cuda_fp16.h>
#include <cstdint>

// Problem constants
#define BATCH 4
#define SEQ   2048
#define DMODEL 1024
#define NHEAD 16
#define HDIM  64
#define MROWS (BATCH * SEQ)          // 8192

// Q prescale: 1/sqrt(HD) * log2(e), folded into stored Q so flash uses exp2
#define QSCALE 0.1803368801111204f

// Scratch (device globals; allocation-free). All fp16.
__device__ __half g_qh[BATCH * NHEAD * SEQ * HDIM];     // [B,H,T,HD] (prescaled)
__device__ __half g_kh[BATCH * NHEAD * SEQ * HDIM];     // [B,H,T,HD]
__device__ __half g_vth[BATCH * NHEAD * HDIM * SEQ];    // [B,H,HD,T] (transposed)
__device__ __half g_attnh[MROWS * DMODEL];              // [B,T,D]
__device__ __half g_hidh[MROWS * DMODEL];               // fp16 hidden
__device__ __half g_wqkvt[3 * DMODEL * DMODEL];         // w_attn^T [3D][D]
__device__ __half g_wpt[DMODEL * DMODEL];               // w_proj^T [D][D]

// ---------------------------------------------------------------------------
// helpers
// ---------------------------------------------------------------------------
__device__ __forceinline__ unsigned smem_u32(const void* p) {
    return (unsigned)__cvta_generic_to_shared(p);
}
__device__ __forceinline__ void cp_async16(unsigned s, const void* g) {
    asm volatile("cp.async.cg.shared.global [%0], [%1], 16;\n" :: "r"(s), "l"(g));
}
#define CP_COMMIT() asm volatile("cp.async.commit_group;\n" ::: "memory")
#define CP_WAIT(n)  asm volatile("cp.async.wait_group %0;\n" :: "n"(n) : "memory")

__device__ __forceinline__ unsigned pack2h(float a, float b) {
    __half2 h = __floats2half2_rn(a, b);
    return *(unsigned*)&h;
}
__device__ __forceinline__ void mma_f16s(float* d, const unsigned* a, const unsigned* b) {
    asm volatile(
        "mma.sync.aligned.m16n8k16.row.col.f32.f16.f16.f32 "
        "{%0,%1,%2,%3},{%4,%5,%6,%7},{%8,%9},{%0,%1,%2,%3};\n"
        : "+f"(d[0]), "+f"(d[1]), "+f"(d[2]), "+f"(d[3])
        : "r"(a[0]), "r"(a[1]), "r"(a[2]), "r"(a[3]), "r"(b[0]), "r"(b[1]));
}
__device__ __forceinline__ void ldm_x4(unsigned* r, unsigned addr) {
    asm volatile(
        "ldmatrix.sync.aligned.m8n8.x4.shared.b16 {%0,%1,%2,%3}, [%4];"
        : "=r"(r[0]), "=r"(r[1]), "=r"(r[2]), "=r"(r[3]) : "r"(addr));
}
__device__ __forceinline__ float fexp2(float x) {
    float y;
    asm("ex2.approx.ftz.f32 %0, %1;" : "=f"(y) : "f"(x));
    return y;
}

// ---------------------------------------------------------------------------
// Prepass 1: fp32 -> fp16 (vectorized)
// ---------------------------------------------------------------------------
__global__ __launch_bounds__(256) void f32_to_f16_kernel(
    const float* __restrict__ src, __half* __restrict__ dst, int n4)
{
    int i = blockIdx.x * blockDim.x + threadIdx.x;
    if (i < n4) {
        float4 v = ((const float4*)src)[i];
        __half2 h0 = __floats2half2_rn(v.x, v.y);
        __half2 h1 = __floats2half2_rn(v.z, v.w);
        ((uint2*)dst)[i] = make_uint2(*(unsigned*)&h0, *(unsigned*)&h1);
    }
}

// ---------------------------------------------------------------------------
// Prepass 2 (merged): transpose+convert both weights in one launch.
// ---------------------------------------------------------------------------
__global__ void transpose_both_kernel(
    const float* __restrict__ w_attn, const float* __restrict__ w_proj)
{
    __shared__ float t[32][33];
    const int z = blockIdx.z;
    const int N = z ? DMODEL : 3 * DMODEL;
    if (z && blockIdx.x >= DMODEL / 32) return;
    const float* src = z ? w_proj : w_attn;
    __half* dst = z ? g_wpt : g_wqkvt;

    int n = blockIdx.x * 32 + threadIdx.x;
    int k = blockIdx.y * 32 + threadIdx.y;
    t[threadIdx.y][threadIdx.x] = src[(size_t)k * N + n];
    __syncthreads();
    int no = blockIdx.x * 32 + threadIdx.y;
    int ko = blockIdx.y * 32 + threadIdx.x;
    dst[(size_t)no * DMODEL + ko] = __float2half_rn(t[threadIdx.x][threadIdx.y]);
}

// ---------------------------------------------------------------------------
// FP16 mma.sync GEMM: block 128x64, BK=64, 4 warps (warp tile 32x64),
// 2-stage cp.async, 48KB static smem, 4 CTAs/SM, ldmatrix feeds.
// ldmatrix addresses hoisted: addr(kc) = base ^ (kc<<5).
// MODE 0: Q values prescaled by QSCALE at store.
// ---------------------------------------------------------------------------
template <int MODE>
__global__ __launch_bounds__(128, 4) void gemm_f16(
    const float* __restrict__ bias,
    float* __restrict__ C,
    int Kdim, int Ndim)
{
    __shared__ __align__(128) __half As[2][128 * 64];   // 2 x 16KB
    __shared__ __align__(128) __half Bs[2][64 * 64];    // 2 x 8KB

    const __half* A  = (MODE == 0) ? g_hidh  : g_attnh;
    const __half* Wt = (MODE == 0) ? g_wqkvt : g_wpt;

    const int m0 = blockIdx.y * 128;
    const int n0 = blockIdx.x * 64;
    const int tid  = threadIdx.x;
    const int lane = tid & 31;
    const int wid  = tid >> 5;
    const int wr = wid * 32;         // warp row offset (4 warps in M)
    const int g  = lane >> 2;
    const int t2 = (lane & 3) * 2;

    const int rA  = lane & 15;
    const int cA  = lane >> 4;
    const int selB = lane >> 3;
    const int rBo  = ((selB >> 1) << 3) + (lane & 7);
    const int cB   = selB & 1;

    const unsigned sA[2] = { smem_u32(As[0]), smem_u32(As[1]) };
    const unsigned sB[2] = { smem_u32(Bs[0]), smem_u32(Bs[1]) };

    // kc-invariant ldmatrix base offsets (XOR with kc<<5 per chunk)
    unsigned pA[2], pB[4];
#pragma unroll
    for (int i = 0; i < 2; i++) {
        const int row = wr + i * 16 + rA;
        pA[i] = row * 128 + ((cA ^ (row & 7)) << 4);
    }
#pragma unroll
    for (int jj = 0; jj < 4; jj++) {
        const int row = jj * 16 + rBo;
        pB[jj] = row * 128 + ((cB ^ (row & 7)) << 4);
    }

    float acc[2][8][4];
#pragma unroll
    for (int i = 0; i < 2; i++)
#pragma unroll
        for (int j = 0; j < 8; j++)
#pragma unroll
            for (int r = 0; r < 4; r++) acc[i][j][r] = 0.0f;

#define LOAD_TILE(KT_, ST_)                                                     \
    _Pragma("unroll")                                                           \
    for (int i_ = 0; i_ < 8; i_++) {                                            \
        const int c_ = tid + i_ * 128;                                          \
        const int row_ = c_ >> 3, ch_ = c_ & 7;                                 \
        const unsigned ph_ = row_ * 128 + (((ch_) ^ (row_ & 7)) << 4);          \
        cp_async16(sA[ST_] + ph_, &A[(size_t)(m0 + row_) * Kdim + (KT_) + ch_ * 8]); \
    }                                                                           \
    _Pragma("unroll")                                                           \
    for (int i_ = 0; i_ < 4; i_++) {                                            \
        const int c_ = tid + i_ * 128;                                          \
        const int row_ = c_ >> 3, ch_ = c_ & 7;                                 \
        const unsigned ph_ = row_ * 128 + (((ch_) ^ (row_ & 7)) << 4);          \
        cp_async16(sB[ST_] + ph_, &Wt[(size_t)(n0 + row_) * Kdim + (KT_) + ch_ * 8]); \
    }

    const int KT = Kdim >> 6;
    LOAD_TILE(0, 0);
    CP_COMMIT();

    for (int kt = 0; kt < KT; kt++) {
        const int st = kt & 1;
        CP_WAIT(0);
        __syncthreads();

        if (kt + 1 < KT) {
            LOAD_TILE((kt + 1) << 6, st ^ 1);
            CP_COMMIT();
        }

        const unsigned aAdr0 = sA[st] + pA[0];
        const unsigned aAdr1 = sA[st] + pA[1];
        const unsigned bAdr0 = sB[st] + pB[0];
        const unsigned bAdr1 = sB[st] + pB[1];
        const unsigned bAdr2 = sB[st] + pB[2];
        const unsigned bAdr3 = sB[st] + pB[3];

#pragma unroll
        for (int kc = 0; kc < 4; kc++) {
            const unsigned kx = kc << 5;
            unsigned af[2][4], bf[8][2];
            ldm_x4(af[0], aAdr0 ^ kx);
            ldm_x4(af[1], aAdr1 ^ kx);
            {
                unsigned q[4];
                ldm_x4(q, bAdr0 ^ kx);
                bf[0][0] = q[0]; bf[0][1] = q[1]; bf[1][0] = q[2]; bf[1][1] = q[3];
                ldm_x4(q, bAdr1 ^ kx);
                bf[2][0] = q[0]; bf[2][1] = q[1]; bf[3][0] = q[2]; bf[3][1] = q[3];
                ldm_x4(q, bAdr2 ^ kx);
                bf[4][0] = q[0]; bf[4][1] = q[1]; bf[5][0] = q[2]; bf[5][1] = q[3];
                ldm_x4(q, bAdr3 ^ kx);
                bf[6][0] = q[0]; bf[6][1] = q[1]; bf[7][0] = q[2]; bf[7][1] = q[3];
            }
#pragma unroll
            for (int i = 0; i < 2; i++)
#pragma unroll
                for (int j = 0; j < 8; j++) mma_f16s(acc[i][j], af[i], bf[j]);
        }
    }

#pragma unroll
    for (int i = 0; i < 2; i++) {
#pragma unroll
        for (int rr = 0; rr < 2; rr++) {
            const int row = m0 + wr + i * 16 + g + rr * 8;
#pragma unroll
            for (int j = 0; j < 8; j++) {
                const int col = n0 + j * 8 + t2;
                const float v0 = acc[i][j][rr * 2 + 0] + bias[col];
                const float v1 = acc[i][j][rr * 2 + 1] + bias[col + 1];
                if (MODE == 0) {
                    const int which = col >> 10;       // 0=q,1=k,2=v
                    const int d  = col & 1023;
                    const int h  = d >> 6;
                    const int hd = d & 63;
                    const int b  = row >> 11;
                    const int t  = row & 2047;
                    if (which < 2) {
                        __half* dst = (which == 0) ? g_qh : g_kh;
                        const float s = (which == 0) ? QSCALE : 1.0f;
                        const size_t idx =
                            (((size_t)(b * NHEAD + h)) * SEQ + t) * HDIM + hd;
                        __half2 hv = __floats2half2_rn(v0 * s, v1 * s);
                        *(__half2*)&dst[idx] = hv;
                    } else {
                        const size_t idx =
                            (((size_t)(b * NHEAD + h)) * HDIM + hd) * SEQ + t;
                        g_vth[idx]       = __float2half_rn(v0);
                        g_vth[idx + SEQ] = __float2half_rn(v1);
                    }
                } else {
                    *(float2*)&C[(size_t)row * Ndim + col] = make_float2(v0, v1);
                }
            }
        }
    }
#undef LOAD_TILE
}

// ---------------------------------------------------------------------------
// Causal flash attention: Q tile 64, key tile 128, 128 threads (4 warps),
// double-buffered cp.async, 64KB dynamic smem, 3 CTAs/SM.
// Q prescaled by 1/sqrt(HD)*log2e -> softmax via exp2, zero scale muls.
// One __syncthreads per tile (end-of-loop barrier proven redundant).
// ---------------------------------------------------------------------------
__global__ __launch_bounds__(128, 3) void flash_f16()
{
    extern __shared__ __align__(128) unsigned char fdsm_raw[];
    const unsigned base = (smem_u32(fdsm_raw) + 127u) & ~127u;
    const unsigned ksB[2] = { base, base + 16384 };
    const unsigned vtB[2][2] = {
        { base + 32768, base + 40960 },
        { base + 49152, base + 57344 }
    };

    const int qTile = blockIdx.x;
    const int bh    = blockIdx.y;

    const __half* Qh  = g_qh  + (size_t)bh * SEQ * HDIM;
    const __half* Kh  = g_kh  + (size_t)bh * SEQ * HDIM;
    const __half* Vth = g_vth + (size_t)bh * HDIM * SEQ;

    const int tid  = threadIdx.x;
    const int lane = tid & 31;
    const int wid  = tid >> 5;
    const int g    = lane >> 2;
    const int t2   = (lane & 3) * 2;
    const int q0   = qTile * 64;
    const int qr   = q0 + wid * 16 + g;

    const int selB = lane >> 3;
    const int rBo  = ((selB >> 1) << 3) + (lane & 7);
    const int cB   = selB & 1;

    unsigned pK[8];
#pragma unroll
    for (int jj = 0; jj < 8; jj++) {
        const int row = jj * 16 + rBo;
        pK[jj] = row * 128 + ((cB ^ (row & 7)) << 4);
    }

    // preload Q fragments (prescaled; 4 k16-chunks over HD=64)
    unsigned qf[4][4];
#pragma unroll
    for (int kc = 0; kc < 4; kc++) {
        const int ko = kc * 16 + t2;
        qf[kc][0] = *(const unsigned*)&Qh[(size_t)qr * HDIM + ko];
        qf[kc][1] = *(const unsigned*)&Qh[(size_t)(qr + 8) * HDIM + ko];
        qf[kc][2] = *(const unsigned*)&Qh[(size_t)qr * HDIM + ko + 8];
        qf[kc][3] = *(const unsigned*)&Qh[(size_t)(qr + 8) * HDIM + ko + 8];
    }

    float oacc[8][4];
#pragma unroll
    for (int j = 0; j < 8; j++)
#pragma unroll
        for (int r = 0; r < 4; r++) oacc[j][r] = 0.0f;
    float m0r = -1e30f, m1r = -1e30f, l0r = 0.0f, l1r = 0.0f;

#define LOAD_KV(K0_, ST_)                                                       \
    _Pragma("unroll")                                                           \
    for (int i_ = 0; i_ < 8; i_++) {                                            \
        const int c_ = tid + i_ * 128;                                          \
        const int r_ = c_ >> 3, ch_ = c_ & 7;                                   \
        const unsigned ph_ = r_ * 128 + (((ch_) ^ (r_ & 7)) << 4);              \
        cp_async16(ksB[ST_] + ph_, &Kh[(size_t)((K0_) + r_) * HDIM + ch_ * 8]); \
    }                                                                           \
    _Pragma("unroll")                                                           \
    for (int hf_ = 0; hf_ < 2; hf_++) {                                         \
        _Pragma("unroll")                                                       \
        for (int i_ = 0; i_ < 4; i_++) {                                        \
            const int c_ = tid + i_ * 128;                                      \
            const int r_ = c_ >> 3, ch_ = c_ & 7;                               \
            const unsigned ph_ = r_ * 128 + (((ch_) ^ (r_ & 7)) << 4);          \
            cp_async16(vtB[ST_][hf_] + ph_,                                     \
                       &Vth[(size_t)r_ * SEQ + (K0_) + hf_ * 64 + ch_ * 8]);    \
        }                                                                       \
    }

    const int ktN = (qTile >> 1) + 1;   // 128-key tiles
    LOAD_KV(0, 0);
    CP_COMMIT();

    for (int kt = 0; kt < ktN; kt++) {
        const int st = kt & 1;
        CP_WAIT(0);
        __syncthreads();   // tile kt resident & visible; prior iter fully done

        if (kt + 1 < ktN) {
            LOAD_KV((kt + 1) * 128, st ^ 1);
            CP_COMMIT();
        }

        // S = Q @ K^T  (already in log2-softmax domain via Q prescale)
        float sacc[16][4];
#pragma unroll
        for (int j = 0; j < 16; j++)
#pragma unroll
            for (int r = 0; r < 4; r++) sacc[j][r] = 0.0f;

#pragma unroll
        for (int kc = 0; kc < 4; kc++) {
            const unsigned kx = kc << 5;
            unsigned bf[16][2];
#pragma unroll
            for (int jj = 0; jj < 8; jj++) {
                unsigned q[4];
                ldm_x4(q, (ksB[st] + pK[jj]) ^ kx);
                bf[2 * jj][0]     = q[0];
                bf[2 * jj][1]     = q[1];
                bf[2 * jj + 1][0] = q[2];
                bf[2 * jj + 1][1] = q[3];
            }
#pragma unroll
            for (int j = 0; j < 16; j++) mma_f16s(sacc[j], qf[kc], bf[j]);
        }

        // causal mask (last tile only; no scale needed — folded into Q)
        if (kt == ktN - 1) {
            const int r0 = q0 + wid * 16 + g;
            const int r1 = r0 + 8;
            const int kbase = kt * 128;
#pragma unroll
            for (int j = 0; j < 16; j++) {
                const int c = kbase + j * 8 + t2;
                if (c     > r0) sacc[j][0] = -1e30f;
                if (c + 1 > r0) sacc[j][1] = -1e30f;
                if (c     > r1) sacc[j][2] = -1e30f;
                if (c + 1 > r1) sacc[j][3] = -1e30f;
            }
        }

        // online softmax in log2 domain (rows owned by 4-lane groups)
        float rm0 = -1e30f, rm1 = -1e30f;
#pragma unroll
        for (int j = 0; j < 16; j++) {
            rm0 = fmaxf(rm0, fmaxf(sacc[j][0], sacc[j][1]));
            rm1 = fmaxf(rm1, fmaxf(sacc[j][2], sacc[j][3]));
        }
#pragma unroll
        for (int s = 1; s < 4; s <<= 1) {
            rm0 = fmaxf(rm0, __shfl_xor_sync(0xffffffffu, rm0, s));
            rm1 = fmaxf(rm1, __shfl_xor_sync(0xffffffffu, rm1, s));
        }
        const float mn0 = fmaxf(m0r, rm0);
        const float mn1 = fmaxf(m1r, rm1);
        const float al0 = fexp2(m0r - mn0);
        const float al1 = fexp2(m1r - mn1);
        float rs0 = 0.0f, rs1 = 0.0f;
#pragma unroll
        for (int j = 0; j < 16; j++) {
            sacc[j][0] = fexp2(sacc[j][0] - mn0);
            sacc[j][1] = fexp2(sacc[j][1] - mn0);
            sacc[j][2] = fexp2(sacc[j][2] - mn1);
            sacc[j][3] = fexp2(sacc[j][3] - mn1);
            rs0 += sacc[j][0] + sacc[j][1];
            rs1 += sacc[j][2] + sacc[j][3];
        }
#pragma unroll
        for (int s = 1; s < 4; s <<= 1) {
            rs0 += __shfl_xor_sync(0xffffffffu, rs0, s);
            rs1 += __shfl_xor_sync(0xffffffffu, rs1, s);
        }
        l0r = l0r * al0 + rs0;
        l1r = l1r * al1 + rs1;
        m0r = mn0;
        m1r = mn1;
#pragma unroll
        for (int j = 0; j < 8; j++) {
            oacc[j][0] *= al0;
            oacc[j][1] *= al0;
            oacc[j][2] *= al1;
            oacc[j][3] *= al1;
        }

        // O += P @ V : 8 k16-chunks over 128 keys; V half = kc>>2
        const unsigned v0Adr = vtB[st][0];
        const unsigned v1Adr = vtB[st][1];
#pragma unroll
        for (int kc = 0; kc < 8; kc++) {
            unsigned af[4];
            af[0] = pack2h(sacc[2 * kc][0],     sacc[2 * kc][1]);
            af[1] = pack2h(sacc[2 * kc][2],     sacc[2 * kc][3]);
            af[2] = pack2h(sacc[2 * kc + 1][0], sacc[2 * kc + 1][1]);
            af[3] = pack2h(sacc[2 * kc + 1][2], sacc[2 * kc + 1][3]);
            const unsigned vbase = (kc < 4) ? v0Adr : v1Adr;
            const unsigned kx = (kc & 3) << 5;
            unsigned bf[8][2];
#pragma unroll
            for (int jj = 0; jj < 4; jj++) {
                unsigned q[4];
                ldm_x4(q, (vbase + pK[jj]) ^ kx);
                bf[2 * jj][0]     = q[0];
                bf[2 * jj][1]     = q[1];
                bf[2 * jj + 1][0] = q[2];
                bf[2 * jj + 1][1] = q[3];
            }
#pragma unroll
            for (int j = 0; j < 8; j++) mma_f16s(oacc[j], af, bf[j]);
        }
        // no end barrier: next iter's top sync (after its CP_WAIT) already
        // orders all warps past this iteration before any buffer refill.
    }
#undef LOAD_KV

    // write merged-head output [B,T,D] as fp16 (proj consumes fp16)
    const int b = bh >> 4;
    const int h = bh & 15;
    const float il0 = 1.0f / l0r;
    const float il1 = 1.0f / l1r;
    const int t0 = q0 + wid * 16 + g;
    __half* base0 = g_attnh + ((size_t)(b * SEQ + t0)) * DMODEL + h * HDIM;
    __half* base1 = g_attnh + ((size_t)(b * SEQ + t0 + 8)) * DMODEL + h * HDIM;
#pragma unroll
    for (int j = 0; j < 8; j++) {
        const int c = j * 8 + t2;
        __half2 h0 = __floats2half2_rn(oacc[j][0] * il0, oacc[j][1] * il0);
        __half2 h1 = __floats2half2_rn(oacc[j][2] * il1, oacc[j][3] * il1);
        *(__half2*)&base0[c] = h0;
        *(__half2*)&base1[c] = h1;
    }
}

// ---------------------------------------------------------------------------
// kernel_launch
// inputs: 0 hidden_states [B,T,D] f32, 1 w_attn [D,3D], 2 b_attn [3D],
//         3 w_proj [D,D], 4 b_proj [D]; output [B,T,D] f32
// ---------------------------------------------------------------------------
extern "C" void kernel_launch(void* const* d_in, const int* in_sizes, int n_in,
                              void* d_out, int out_size)
{
    const float* hidden = (const float*)d_in[0];
    const float* w_attn = (const float*)d_in[1];
    const float* b_attn = (const float*)d_in[2];
    const float* w_proj = (const float*)d_in[3];
    const float* b_proj = (const float*)d_in[4];
    float* out = (float*)d_out;

    const int FDSM = 65536 + 128;   // flash: 64KB payload + align slack
    cudaFuncSetAttribute(flash_f16, cudaFuncAttributeMaxDynamicSharedMemorySize, FDSM);

    // 0) prepass: fp16 convert + merged weight transposes
    {
        __half* d_hid; cudaGetSymbolAddress((void**)&d_hid, g_hidh);
        f32_to_f16_kernel<<<(MROWS * DMODEL / 4 + 255) / 256, 256>>>(
            hidden, d_hid, MROWS * DMODEL / 4);
        transpose_both_kernel<<<dim3(3 * DMODEL / 32, DMODEL / 32, 2), dim3(32, 32)>>>(
            w_attn, w_proj);
    }

    // 1) QKV GEMM + bias + head split (Q prescaled)
    gemm_f16<0><<<dim3(3 * DMODEL / 64, MROWS / 128), 128>>>(
        b_attn, nullptr, DMODEL, 3 * DMODEL);

    // 2) causal flash attention (q-tile 64, key-tile 128, exp2 softmax)
    flash_f16<<<dim3(SEQ / 64, BATCH * NHEAD), 128, FDSM>>>();

    // 3) output projection + bias (fp32 out)
    gemm_f16<1><<<dim3(DMODEL / 64, MROWS / 128), 128>>>(
        b_proj, out, DMODEL, DMODEL);
}

// round 15
// speedup vs baseline: 1.1248x; 1.0041x over previous
#include <cuda_runtime.h>
#include <cuda_fp16.h>
#include <cstdint>

// Problem constants
#define BATCH 4
#define SEQ   2048
#define DMODEL 1024
#define NHEAD 16
#define HDIM  64
#define MROWS (BATCH * SEQ)          // 8192

// Q prescale: 1/sqrt(HD) * log2(e), folded into stored Q so flash uses exp2
#define QSCALE 0.1803368801111204f

// Scratch (device globals; allocation-free). All fp16.
__device__ __half g_qh[BATCH * NHEAD * SEQ * HDIM];     // [B,H,T,HD] (prescaled)
__device__ __half g_kh[BATCH * NHEAD * SEQ * HDIM];     // [B,H,T,HD]
__device__ __half g_vth[BATCH * NHEAD * HDIM * SEQ];    // [B,H,HD,T] (transposed)
__device__ __half g_attnh[MROWS * DMODEL];              // [B,T,D]
__device__ __half g_hidh[MROWS * DMODEL];               // fp16 hidden
__device__ __half g_wqkvt[3 * DMODEL * DMODEL];         // w_attn^T [3D][D]
__device__ __half g_wpt[DMODEL * DMODEL];               // w_proj^T [D][D]

// ---------------------------------------------------------------------------
// helpers
// ---------------------------------------------------------------------------
__device__ __forceinline__ unsigned smem_u32(const void* p) {
    return (unsigned)__cvta_generic_to_shared(p);
}
__device__ __forceinline__ void cp_async16(unsigned s, const void* g) {
    asm volatile("cp.async.cg.shared.global [%0], [%1], 16;\n" :: "r"(s), "l"(g));
}
#define CP_COMMIT() asm volatile("cp.async.commit_group;\n" ::: "memory")
#define CP_WAIT(n)  asm volatile("cp.async.wait_group %0;\n" :: "n"(n) : "memory")

__device__ __forceinline__ unsigned pack2h(float a, float b) {
    __half2 h = __floats2half2_rn(a, b);
    return *(unsigned*)&h;
}
__device__ __forceinline__ void mma_f16s(float* d, const unsigned* a, const unsigned* b) {
    asm volatile(
        "mma.sync.aligned.m16n8k16.row.col.f32.f16.f16.f32 "
        "{%0,%1,%2,%3},{%4,%5,%6,%7},{%8,%9},{%0,%1,%2,%3};\n"
        : "+f"(d[0]), "+f"(d[1]), "+f"(d[2]), "+f"(d[3])
        : "r"(a[0]), "r"(a[1]), "r"(a[2]), "r"(a[3]), "r"(b[0]), "r"(b[1]));
}
__device__ __forceinline__ void ldm_x4(unsigned* r, unsigned addr) {
    asm volatile(
        "ldmatrix.sync.aligned.m8n8.x4.shared.b16 {%0,%1,%2,%3}, [%4];"
        : "=r"(r[0]), "=r"(r[1]), "=r"(r[2]), "=r"(r[3]) : "r"(addr));
}
__device__ __forceinline__ float fexp2(float x) {
    float y;
    asm("ex2.approx.ftz.f32 %0, %1;" : "=f"(y) : "f"(x));
    return y;
}

// ---------------------------------------------------------------------------
// Prepass 1: fp32 -> fp16 (vectorized)
// ---------------------------------------------------------------------------
__global__ __launch_bounds__(256) void f32_to_f16_kernel(
    const float* __restrict__ src, __half* __restrict__ dst, int n4)
{
    int i = blockIdx.x * blockDim.x + threadIdx.x;
    if (i < n4) {
        float4 v = ((const float4*)src)[i];
        __half2 h0 = __floats2half2_rn(v.x, v.y);
        __half2 h1 = __floats2half2_rn(v.z, v.w);
        ((uint2*)dst)[i] = make_uint2(*(unsigned*)&h0, *(unsigned*)&h1);
    }
}

// ---------------------------------------------------------------------------
// Prepass 2 (merged): transpose+convert both weights in one launch.
// ---------------------------------------------------------------------------
__global__ void transpose_both_kernel(
    const float* __restrict__ w_attn, const float* __restrict__ w_proj)
{
    __shared__ float t[32][33];
    const int z = blockIdx.z;
    const int N = z ? DMODEL : 3 * DMODEL;
    if (z && blockIdx.x >= DMODEL / 32) return;
    const float* src = z ? w_proj : w_attn;
    __half* dst = z ? g_wpt : g_wqkvt;

    int n = blockIdx.x * 32 + threadIdx.x;
    int k = blockIdx.y * 32 + threadIdx.y;
    t[threadIdx.y][threadIdx.x] = src[(size_t)k * N + n];
    __syncthreads();
    int no = blockIdx.x * 32 + threadIdx.y;
    int ko = blockIdx.y * 32 + threadIdx.x;
    dst[(size_t)no * DMODEL + ko] = __float2half_rn(t[threadIdx.x][threadIdx.y]);
}

// ---------------------------------------------------------------------------
// FP16 mma.sync GEMM: block 128x64, BK=64, 4 warps (warp tile 32x64),
// 2-stage cp.async, 48KB static smem, 4 CTAs/SM, ldmatrix feeds.
// ldmatrix addresses hoisted: addr(kc) = base ^ (kc<<5).
// MODE 0: Q values prescaled by QSCALE at store.
// ---------------------------------------------------------------------------
template <int MODE>
__global__ __launch_bounds__(128, 4) void gemm_f16(
    const float* __restrict__ bias,
    float* __restrict__ C,
    int Kdim, int Ndim)
{
    __shared__ __align__(128) __half As[2][128 * 64];   // 2 x 16KB
    __shared__ __align__(128) __half Bs[2][64 * 64];    // 2 x 8KB

    const __half* A  = (MODE == 0) ? g_hidh  : g_attnh;
    const __half* Wt = (MODE == 0) ? g_wqkvt : g_wpt;

    const int m0 = blockIdx.y * 128;
    const int n0 = blockIdx.x * 64;
    const int tid  = threadIdx.x;
    const int lane = tid & 31;
    const int wid  = tid >> 5;
    const int wr = wid * 32;         // warp row offset (4 warps in M)
    const int g  = lane >> 2;
    const int t2 = (lane & 3) * 2;

    const int rA  = lane & 15;
    const int cA  = lane >> 4;
    const int selB = lane >> 3;
    const int rBo  = ((selB >> 1) << 3) + (lane & 7);
    const int cB   = selB & 1;

    const unsigned sA[2] = { smem_u32(As[0]), smem_u32(As[1]) };
    const unsigned sB[2] = { smem_u32(Bs[0]), smem_u32(Bs[1]) };

    // kc-invariant ldmatrix base offsets (XOR with kc<<5 per chunk)
    unsigned pA[2], pB[4];
#pragma unroll
    for (int i = 0; i < 2; i++) {
        const int row = wr + i * 16 + rA;
        pA[i] = row * 128 + ((cA ^ (row & 7)) << 4);
    }
#pragma unroll
    for (int jj = 0; jj < 4; jj++) {
        const int row = jj * 16 + rBo;
        pB[jj] = row * 128 + ((cB ^ (row & 7)) << 4);
    }

    float acc[2][8][4];
#pragma unroll
    for (int i = 0; i < 2; i++)
#pragma unroll
        for (int j = 0; j < 8; j++)
#pragma unroll
            for (int r = 0; r < 4; r++) acc[i][j][r] = 0.0f;

#define LOAD_TILE(KT_, ST_)                                                     \
    _Pragma("unroll")                                                           \
    for (int i_ = 0; i_ < 8; i_++) {                                            \
        const int c_ = tid + i_ * 128;                                          \
        const int row_ = c_ >> 3, ch_ = c_ & 7;                                 \
        const unsigned ph_ = row_ * 128 + (((ch_) ^ (row_ & 7)) << 4);          \
        cp_async16(sA[ST_] + ph_, &A[(size_t)(m0 + row_) * Kdim + (KT_) + ch_ * 8]); \
    }                                                                           \
    _Pragma("unroll")                                                           \
    for (int i_ = 0; i_ < 4; i_++) {                                            \
        const int c_ = tid + i_ * 128;                                          \
        const int row_ = c_ >> 3, ch_ = c_ & 7;                                 \
        const unsigned ph_ = row_ * 128 + (((ch_) ^ (row_ & 7)) << 4);          \
        cp_async16(sB[ST_] + ph_, &Wt[(size_t)(n0 + row_) * Kdim + (KT_) + ch_ * 8]); \
    }

    const int KT = Kdim >> 6;
    LOAD_TILE(0, 0);
    CP_COMMIT();

    for (int kt = 0; kt < KT; kt++) {
        const int st = kt & 1;
        CP_WAIT(0);
        __syncthreads();

        if (kt + 1 < KT) {
            LOAD_TILE((kt + 1) << 6, st ^ 1);
            CP_COMMIT();
        }

        const unsigned aAdr0 = sA[st] + pA[0];
        const unsigned aAdr1 = sA[st] + pA[1];
        const unsigned bAdr0 = sB[st] + pB[0];
        const unsigned bAdr1 = sB[st] + pB[1];
        const unsigned bAdr2 = sB[st] + pB[2];
        const unsigned bAdr3 = sB[st] + pB[3];

#pragma unroll
        for (int kc = 0; kc < 4; kc++) {
            const unsigned kx = kc << 5;
            unsigned af[2][4], bf[8][2];
            ldm_x4(af[0], aAdr0 ^ kx);
            ldm_x4(af[1], aAdr1 ^ kx);
            {
                unsigned q[4];
                ldm_x4(q, bAdr0 ^ kx);
                bf[0][0] = q[0]; bf[0][1] = q[1]; bf[1][0] = q[2]; bf[1][1] = q[3];
                ldm_x4(q, bAdr1 ^ kx);
                bf[2][0] = q[0]; bf[2][1] = q[1]; bf[3][0] = q[2]; bf[3][1] = q[3];
                ldm_x4(q, bAdr2 ^ kx);
                bf[4][0] = q[0]; bf[4][1] = q[1]; bf[5][0] = q[2]; bf[5][1] = q[3];
                ldm_x4(q, bAdr3 ^ kx);
                bf[6][0] = q[0]; bf[6][1] = q[1]; bf[7][0] = q[2]; bf[7][1] = q[3];
            }
#pragma unroll
            for (int i = 0; i < 2; i++)
#pragma unroll
                for (int j = 0; j < 8; j++) mma_f16s(acc[i][j], af[i], bf[j]);
        }
    }

#pragma unroll
    for (int i = 0; i < 2; i++) {
#pragma unroll
        for (int rr = 0; rr < 2; rr++) {
            const int row = m0 + wr + i * 16 + g + rr * 8;
#pragma unroll
            for (int j = 0; j < 8; j++) {
                const int col = n0 + j * 8 + t2;
                const float v0 = acc[i][j][rr * 2 + 0] + bias[col];
                const float v1 = acc[i][j][rr * 2 + 1] + bias[col + 1];
                if (MODE == 0) {
                    const int which = col >> 10;       // 0=q,1=k,2=v
                    const int d  = col & 1023;
                    const int h  = d >> 6;
                    const int hd = d & 63;
                    const int b  = row >> 11;
                    const int t  = row & 2047;
                    if (which < 2) {
                        __half* dst = (which == 0) ? g_qh : g_kh;
                        const float s = (which == 0) ? QSCALE : 1.0f;
                        const size_t idx =
                            (((size_t)(b * NHEAD + h)) * SEQ + t) * HDIM + hd;
                        __half2 hv = __floats2half2_rn(v0 * s, v1 * s);
                        *(__half2*)&dst[idx] = hv;
                    } else {
                        const size_t idx =
                            (((size_t)(b * NHEAD + h)) * HDIM + hd) * SEQ + t;
                        g_vth[idx]       = __float2half_rn(v0);
                        g_vth[idx + SEQ] = __float2half_rn(v1);
                    }
                } else {
                    *(float2*)&C[(size_t)row * Ndim + col] = make_float2(v0, v1);
                }
            }
        }
    }
#undef LOAD_TILE
}

// ---------------------------------------------------------------------------
// Causal flash attention: Q tile 64, key tile 128, 128 threads (4 warps),
// double-buffered cp.async, 64KB dynamic smem, 3 CTAs/SM.
// Q prescaled -> exp2 softmax. Row-sum l computed ON THE TENSOR PIPE via an
// extra mma with a constant all-ones B fragment (lacc), removing the fp-add
// chain + shuffle reduction per tile.
// ---------------------------------------------------------------------------
__global__ __launch_bounds__(128, 3) void flash_f16()
{
    extern __shared__ __align__(128) unsigned char fdsm_raw[];
    const unsigned base = (smem_u32(fdsm_raw) + 127u) & ~127u;
    const unsigned ksB[2] = { base, base + 16384 };
    const unsigned vtB[2][2] = {
        { base + 32768, base + 40960 },
        { base + 49152, base + 57344 }
    };

    const int qTile = blockIdx.x;
    const int bh    = blockIdx.y;

    const __half* Qh  = g_qh  + (size_t)bh * SEQ * HDIM;
    const __half* Kh  = g_kh  + (size_t)bh * SEQ * HDIM;
    const __half* Vth = g_vth + (size_t)bh * HDIM * SEQ;

    const int tid  = threadIdx.x;
    const int lane = tid & 31;
    const int wid  = tid >> 5;
    const int g    = lane >> 2;
    const int t2   = (lane & 3) * 2;
    const int q0   = qTile * 64;
    const int qr   = q0 + wid * 16 + g;

    const int selB = lane >> 3;
    const int rBo  = ((selB >> 1) << 3) + (lane & 7);
    const int cB   = selB & 1;

    unsigned pK[8];
#pragma unroll
    for (int jj = 0; jj < 8; jj++) {
        const int row = jj * 16 + rBo;
        pK[jj] = row * 128 + ((cB ^ (row & 7)) << 4);
    }

    // preload Q fragments (prescaled; 4 k16-chunks over HD=64)
    unsigned qf[4][4];
#pragma unroll
    for (int kc = 0; kc < 4; kc++) {
        const int ko = kc * 16 + t2;
        qf[kc][0] = *(const unsigned*)&Qh[(size_t)qr * HDIM + ko];
        qf[kc][1] = *(const unsigned*)&Qh[(size_t)(qr + 8) * HDIM + ko];
        qf[kc][2] = *(const unsigned*)&Qh[(size_t)qr * HDIM + ko + 8];
        qf[kc][3] = *(const unsigned*)&Qh[(size_t)(qr + 8) * HDIM + ko + 8];
    }

    float oacc[8][4];
#pragma unroll
    for (int j = 0; j < 8; j++)
#pragma unroll
        for (int r = 0; r < 4; r++) oacc[j][r] = 0.0f;
    float lacc[4] = {0.0f, 0.0f, 0.0f, 0.0f};   // row-sum accumulator (P @ ones)
    float m0r = -1e30f, m1r = -1e30f;

    const unsigned ones_bf[2] = { 0x3C003C00u, 0x3C003C00u };   // (1.0h,1.0h) x2

#define LOAD_KV(K0_, ST_)                                                       \
    _Pragma("unroll")                                                           \
    for (int i_ = 0; i_ < 8; i_++) {                                            \
        const int c_ = tid + i_ * 128;                                          \
        const int r_ = c_ >> 3, ch_ = c_ & 7;                                   \
        const unsigned ph_ = r_ * 128 + (((ch_) ^ (r_ & 7)) << 4);              \
        cp_async16(ksB[ST_] + ph_, &Kh[(size_t)((K0_) + r_) * HDIM + ch_ * 8]); \
    }                                                                           \
    _Pragma("unroll")                                                           \
    for (int hf_ = 0; hf_ < 2; hf_++) {                                         \
        _Pragma("unroll")                                                       \
        for (int i_ = 0; i_ < 4; i_++) {                                        \
            const int c_ = tid + i_ * 128;                                      \
            const int r_ = c_ >> 3, ch_ = c_ & 7;                               \
            const unsigned ph_ = r_ * 128 + (((ch_) ^ (r_ & 7)) << 4);          \
            cp_async16(vtB[ST_][hf_] + ph_,                                     \
                       &Vth[(size_t)r_ * SEQ + (K0_) + hf_ * 64 + ch_ * 8]);    \
        }                                                                       \
    }

    const int ktN = (qTile >> 1) + 1;   // 128-key tiles
    LOAD_KV(0, 0);
    CP_COMMIT();

    for (int kt = 0; kt < ktN; kt++) {
        const int st = kt & 1;
        CP_WAIT(0);
        __syncthreads();   // tile kt resident & visible; prior iter fully done

        if (kt + 1 < ktN) {
            LOAD_KV((kt + 1) * 128, st ^ 1);
            CP_COMMIT();
        }

        // S = Q @ K^T  (already in log2-softmax domain via Q prescale)
        float sacc[16][4];
#pragma unroll
        for (int j = 0; j < 16; j++)
#pragma unroll
            for (int r = 0; r < 4; r++) sacc[j][r] = 0.0f;

#pragma unroll
        for (int kc = 0; kc < 4; kc++) {
            const unsigned kx = kc << 5;
            unsigned bf[16][2];
#pragma unroll
            for (int jj = 0; jj < 8; jj++) {
                unsigned q[4];
                ldm_x4(q, (ksB[st] + pK[jj]) ^ kx);
                bf[2 * jj][0]     = q[0];
                bf[2 * jj][1]     = q[1];
                bf[2 * jj + 1][0] = q[2];
                bf[2 * jj + 1][1] = q[3];
            }
#pragma unroll
            for (int j = 0; j < 16; j++) mma_f16s(sacc[j], qf[kc], bf[j]);
        }

        // causal mask (last tile only; no scale — folded into Q)
        if (kt == ktN - 1) {
            const int r0 = q0 + wid * 16 + g;
            const int r1 = r0 + 8;
            const int kbase = kt * 128;
#pragma unroll
            for (int j = 0; j < 16; j++) {
                const int c = kbase + j * 8 + t2;
                if (c     > r0) sacc[j][0] = -1e30f;
                if (c + 1 > r0) sacc[j][1] = -1e30f;
                if (c     > r1) sacc[j][2] = -1e30f;
                if (c + 1 > r1) sacc[j][3] = -1e30f;
            }
        }

        // online softmax max (rows owned by 4-lane groups; xor-reduce 1,2)
        float rm0 = -1e30f, rm1 = -1e30f;
#pragma unroll
        for (int j = 0; j < 16; j++) {
            rm0 = fmaxf(rm0, fmaxf(sacc[j][0], sacc[j][1]));
            rm1 = fmaxf(rm1, fmaxf(sacc[j][2], sacc[j][3]));
        }
#pragma unroll
        for (int s = 1; s < 4; s <<= 1) {
            rm0 = fmaxf(rm0, __shfl_xor_sync(0xffffffffu, rm0, s));
            rm1 = fmaxf(rm1, __shfl_xor_sync(0xffffffffu, rm1, s));
        }
        const float mn0 = fmaxf(m0r, rm0);
        const float mn1 = fmaxf(m1r, rm1);
        const float al0 = fexp2(m0r - mn0);
        const float al1 = fexp2(m1r - mn1);
        m0r = mn0;
        m1r = mn1;
        // p = exp2(s - m); l handled by ones-mma below (no fp-add chain)
#pragma unroll
        for (int j = 0; j < 16; j++) {
            sacc[j][0] = fexp2(sacc[j][0] - mn0);
            sacc[j][1] = fexp2(sacc[j][1] - mn0);
            sacc[j][2] = fexp2(sacc[j][2] - mn1);
            sacc[j][3] = fexp2(sacc[j][3] - mn1);
        }
#pragma unroll
        for (int j = 0; j < 8; j++) {
            oacc[j][0] *= al0;
            oacc[j][1] *= al0;
            oacc[j][2] *= al1;
            oacc[j][3] *= al1;
        }
        lacc[0] *= al0;
        lacc[1] *= al0;
        lacc[2] *= al1;
        lacc[3] *= al1;

        // O += P @ V ; l += P @ ones (tensor-pipe row sum, cross-lane free)
        const unsigned v0Adr = vtB[st][0];
        const unsigned v1Adr = vtB[st][1];
#pragma unroll
        for (int kc = 0; kc < 8; kc++) {
            unsigned af[4];
            af[0] = pack2h(sacc[2 * kc][0],     sacc[2 * kc][1]);
            af[1] = pack2h(sacc[2 * kc][2],     sacc[2 * kc][3]);
            af[2] = pack2h(sacc[2 * kc + 1][0], sacc[2 * kc + 1][1]);
            af[3] = pack2h(sacc[2 * kc + 1][2], sacc[2 * kc + 1][3]);
            const unsigned vbase = (kc < 4) ? v0Adr : v1Adr;
            const unsigned kx = (kc & 3) << 5;
            unsigned bf[8][2];
#pragma unroll
            for (int jj = 0; jj < 4; jj++) {
                unsigned q[4];
                ldm_x4(q, (vbase + pK[jj]) ^ kx);
                bf[2 * jj][0]     = q[0];
                bf[2 * jj][1]     = q[1];
                bf[2 * jj + 1][0] = q[2];
                bf[2 * jj + 1][1] = q[3];
            }
#pragma unroll
            for (int j = 0; j < 8; j++) mma_f16s(oacc[j], af, bf[j]);
            mma_f16s(lacc, af, ones_bf);
        }
        // no end barrier: next iter's top sync already orders all warps.
    }
#undef LOAD_KV

    // write merged-head output [B,T,D] as fp16 (proj consumes fp16)
    const int b = bh >> 4;
    const int h = bh & 15;
    const float il0 = 1.0f / lacc[0];
    const float il1 = 1.0f / lacc[2];
    const int t0 = q0 + wid * 16 + g;
    __half* base0 = g_attnh + ((size_t)(b * SEQ + t0)) * DMODEL + h * HDIM;
    __half* base1 = g_attnh + ((size_t)(b * SEQ + t0 + 8)) * DMODEL + h * HDIM;
#pragma unroll
    for (int j = 0; j < 8; j++) {
        const int c = j * 8 + t2;
        __half2 h0 = __floats2half2_rn(oacc[j][0] * il0, oacc[j][1] * il0);
        __half2 h1 = __floats2half2_rn(oacc[j][2] * il1, oacc[j][3] * il1);
        *(__half2*)&base0[c] = h0;
        *(__half2*)&base1[c] = h1;
    }
}

// ---------------------------------------------------------------------------
// kernel_launch
// inputs: 0 hidden_states [B,T,D] f32, 1 w_attn [D,3D], 2 b_attn [3D],
//         3 w_proj [D,D], 4 b_proj [D]; output [B,T,D] f32
// ---------------------------------------------------------------------------
extern "C" void kernel_launch(void* const* d_in, const int* in_sizes, int n_in,
                              void* d_out, int out_size)
{
    const float* hidden = (const float*)d_in[0];
    const float* w_attn = (const float*)d_in[1];
    const float* b_attn = (const float*)d_in[2];
    const float* w_proj = (const float*)d_in[3];
    const float* b_proj = (const float*)d_in[4];
    float* out = (float*)d_out;

    const int FDSM = 65536 + 128;   // flash: 64KB payload + align slack
    cudaFuncSetAttribute(flash_f16, cudaFuncAttributeMaxDynamicSharedMemorySize, FDSM);

    // 0) prepass: fp16 convert + merged weight transposes
    {
        __half* d_hid; cudaGetSymbolAddress((void**)&d_hid, g_hidh);
        f32_to_f16_kernel<<<(MROWS * DMODEL / 4 + 255) / 256, 256>>>(
            hidden, d_hid, MROWS * DMODEL / 4);
        transpose_both_kernel<<<dim3(3 * DMODEL / 32, DMODEL / 32, 2), dim3(32, 32)>>>(
            w_attn, w_proj);
    }

    // 1) QKV GEMM + bias + head split (Q prescaled)
    gemm_f16<0><<<dim3(3 * DMODEL / 64, MROWS / 128), 128>>>(
        b_attn, nullptr, DMODEL, 3 * DMODEL);

    // 2) causal flash attention (exp2 softmax, tensor-pipe row sums)
    flash_f16<<<dim3(SEQ / 64, BATCH * NHEAD), 128, FDSM>>>();

    // 3) output projection + bias (fp32 out)
    gemm_f16<1><<<dim3(DMODEL / 64, MROWS / 128), 128>>>(
        b_proj, out, DMODEL, DMODEL);
}